// round 7
// baseline (speedup 1.0000x reference)
#include <cuda_runtime.h>

#define Bq 8
#define Cq 64
#define CIq 32
#define Nq 2304          // 48*48
#define NP1 2305
#define TILES 36         // 2304/64
#define NTILE (Bq*TILES) // 288
#define NCH 72           // suffix-scan chunks per batch
#define CHSZ 32
#define GRID 148
#define NTHR 512
#define NBUCK 2048

// ---------------- scratch (__device__ globals; no allocations) ----------------
__device__ float s_a[Bq*Nq];
__device__ float s_b[Bq*Nq];
__device__ float s_gx[Bq*Nq*CIq];          // [b][n][i]
__device__ float s_keys[Bq*Nq];            // sorted b ascending
__device__ int   s_perm[Bq*Nq];
__device__ int   s_kstar[Bq*Nq];
__device__ float s_ctg[Bq*NCH*CIq];        // chunk totals (g)
__device__ float s_ctbg[Bq*NCH*CIq];       // chunk totals (b*g)
__device__ float s_Sg[Bq*NP1*CIq];         // inclusive suffix sums
__device__ float s_Sbg[Bq*NP1*CIq];
__device__ float s_wy[Bq*Cq*Nq];           // pre-BN output
__device__ float s_part[NTILE*Cq*2];       // per-tile (sum, sumsq)

// grid barrier state
__device__ unsigned g_bar = 0;
__device__ volatile unsigned g_gen = 0;

__device__ __forceinline__ void gsync() {
    __syncthreads();
    if (threadIdx.x == 0) {
        __threadfence();
        unsigned gen = g_gen;
        if (atomicAdd(&g_bar, 1u) == gridDim.x - 1) {
            g_bar = 0;
            __threadfence();
            g_gen = gen + 1;
        } else {
            while (g_gen == gen) { __nanosleep(32); }
        }
        __threadfence();
    }
    __syncthreads();
}

__global__ __launch_bounds__(NTHR, 1) void fused_nonlocal(
    const float* __restrict__ x,
    const float* __restrict__ g_w,  const float* __restrict__ g_b,
    const float* __restrict__ th_w, const float* __restrict__ th_b,
    const float* __restrict__ ph_w, const float* __restrict__ ph_b,
    const float* __restrict__ cp_wt, const float* __restrict__ cp_wp,
    const float* __restrict__ W_w,  const float* __restrict__ W_b,
    const float* __restrict__ bn_g, const float* __restrict__ bn_b,
    float* __restrict__ out)
{
    __shared__ __align__(16) unsigned char SM[35840];
    int t = threadIdx.x;

    // ========== P0: b scores only (4 threads per position; 144 blocks) ==========
    if (blockIdx.x < 144) {
        float* wbs  = (float*)SM;          // 64
        float* cstp = (float*)(SM + 256);  // 1
        if (t < 64) {
            float sb = 0.f;
            #pragma unroll
            for (int i = 0; i < CIq; i++)
                sb = fmaf(cp_wp[i], ph_w[i*Cq + t], sb);
            wbs[t] = sb;
        } else if (t == 64) {
            float cb = 0.f;
            #pragma unroll
            for (int i = 0; i < CIq; i++) cb = fmaf(cp_wp[i], ph_b[i], cb);
            cstp[0] = cb;
        }
        __syncthreads();
        int gid = blockIdx.x * NTHR + t;
        int pos = gid >> 2, sub = gid & 3;
        int b = pos / Nq, n = pos - b*Nq;
        const float* xb = x + b*Cq*Nq + n;
        float bb = 0.f;
        #pragma unroll
        for (int k = 0; k < 16; k++) {
            int c = sub*16 + k;
            bb = fmaf(wbs[c], xb[c*Nq], bb);
        }
        bb += __shfl_xor_sync(0xffffffffu, bb, 1);
        bb += __shfl_xor_sync(0xffffffffu, bb, 2);
        if (sub == 0) s_b[pos] = bb + cstp[0];
    }
    gsync();

    // ====== P1: blocks 0-7 bucket-sort b  ||  blocks 8-147 compute gx + a ======
    if (blockIdx.x < Bq) {
        // ---- per-batch bucket sort (deterministic output) ----
        float* kb    = (float*)SM;                 // 2304 floats
        int*   blist = (int*)(SM + 9216);          // 2304 ints
        int*   off   = (int*)(SM + 18432);         // 2049 ints
        int*   cnt   = (int*)(SM + 26640);         // 2048 ints
        int*   aux   = (int*)(SM + 34832);         // 16 ints
        float* auxf  = (float*)(SM + 34912);       // 34 floats

        int b = blockIdx.x;
        int lane = t & 31, w = t >> 5;

        for (int idx = t; idx < NBUCK + 1; idx += NTHR) off[idx] = 0;
        float lmin = 3.4e38f, lmax = -3.4e38f;
        for (int m = t; m < Nq; m += NTHR) {
            float v = s_b[b*Nq + m];
            kb[m] = v;
            lmin = fminf(lmin, v); lmax = fmaxf(lmax, v);
        }
        #pragma unroll
        for (int d = 16; d > 0; d >>= 1) {
            lmin = fminf(lmin, __shfl_xor_sync(0xffffffffu, lmin, d));
            lmax = fmaxf(lmax, __shfl_xor_sync(0xffffffffu, lmax, d));
        }
        if (lane == 0) { auxf[w] = lmin; auxf[16 + w] = lmax; }
        __syncthreads();
        if (t == 0) {
            float mn = auxf[0], mx = auxf[16];
            for (int k = 1; k < 16; k++) {
                mn = fminf(mn, auxf[k]); mx = fmaxf(mx, auxf[16 + k]);
            }
            auxf[32] = mn;
            auxf[33] = (mx > mn) ? ((float)(NBUCK - 1) / (mx - mn)) : 0.f;
        }
        __syncthreads();
        float minv = auxf[32], scale = auxf[33];

        for (int m = t; m < Nq; m += NTHR) {
            int bk = (int)((kb[m] - minv) * scale);
            bk = max(0, min(NBUCK - 1, bk));
            atomicAdd(&off[bk], 1);
        }
        __syncthreads();

        int base = t * 4;
        int h0 = off[base], h1 = off[base+1], h2 = off[base+2], h3 = off[base+3];
        int tsum = h0 + h1 + h2 + h3;
        int inc = tsum;
        #pragma unroll
        for (int d = 1; d < 32; d <<= 1) {
            int v = __shfl_up_sync(0xffffffffu, inc, d);
            if (lane >= d) inc += v;
        }
        if (lane == 31) aux[w] = inc;
        __syncthreads();
        if (t == 0) {
            int acc = 0;
            for (int k = 0; k < 16; k++) { int v = aux[k]; aux[k] = acc; acc += v; }
        }
        __syncthreads();
        int excl = aux[w] + (inc - tsum);
        off[base]     = excl;
        off[base + 1] = excl + h0;
        off[base + 2] = excl + h0 + h1;
        off[base + 3] = excl + h0 + h1 + h2;
        cnt[base] = excl; cnt[base+1] = excl + h0;
        cnt[base+2] = excl + h0 + h1; cnt[base+3] = excl + h0 + h1 + h2;
        if (t == 0) off[NBUCK] = Nq;
        __syncthreads();

        for (int m = t; m < Nq; m += NTHR) {
            int bk = (int)((kb[m] - minv) * scale);
            bk = max(0, min(NBUCK - 1, bk));
            int slot = atomicAdd(&cnt[bk], 1);
            blist[slot] = m;
        }
        __syncthreads();

        for (int m = t; m < Nq; m += NTHR) {
            float v = kb[m];
            int bk = (int)((v - minv) * scale);
            bk = max(0, min(NBUCK - 1, bk));
            int lo = off[bk], hi = off[bk + 1];
            int r = lo;
            for (int j = lo; j < hi; j++) {
                int jm = blist[j];
                float vj = kb[jm];
                r += (vj < v) || (vj == v && jm < m);
            }
            s_keys[b*Nq + r] = v;
            s_perm[b*Nq + r] = m;
        }
    } else {
        // ---- gx projection + a scores (one 64-pos tile per iteration) ----
        float* xs  = (float*)SM;                    // 64*68 = 17408B
        float* gws = (float*)(SM + 17408);          // 32*65 = 8320B
        float* was = (float*)(SM + 25728);          // 64
        float* cst = (float*)(SM + 25984);          // 1
        float* gbs = (float*)(SM + 26000);          // 32

        if (t < 64) {
            float sa = 0.f;
            #pragma unroll
            for (int i = 0; i < CIq; i++)
                sa = fmaf(cp_wt[i], th_w[i*Cq + t], sa);
            was[t] = sa;
        } else if (t == 64) {
            float ca = 0.f;
            #pragma unroll
            for (int i = 0; i < CIq; i++) ca = fmaf(cp_wt[i], th_b[i], ca);
            cst[0] = ca;
        }
        if (t >= 128 && t < 160) gbs[t - 128] = g_b[t - 128];
        for (int idx = t; idx < CIq*Cq; idx += NTHR)
            gws[(idx >> 6)*65 + (idx & 63)] = g_w[idx];
        __syncthreads();

        int i = t & 31, wrp = t >> 5;               // wrp: 0..15
        float gb_i = gbs[i];

        for (int tile = blockIdx.x - 8; tile < NTILE; tile += GRID - 8) {
            int b = tile / TILES, n0 = (tile % TILES)*64;
            float4* xs4 = (float4*)xs;
            const float4* xg = (const float4*)x;
            for (int idx = t; idx < Cq*16; idx += NTHR) {
                int c = idx >> 4, q = idx & 15;
                xs4[c*17 + q] = xg[(((b*Cq + c)*Nq + n0) >> 2) + q];
            }
            __syncthreads();

            float acc[4];
            #pragma unroll
            for (int p = 0; p < 4; p++) acc[p] = gb_i;
            #pragma unroll
            for (int c = 0; c < Cq; c++) {
                float w = gws[i*65 + c];
                float4 xv = *(const float4*)&xs[c*68 + wrp*4];
                acc[0] = fmaf(w, xv.x, acc[0]); acc[1] = fmaf(w, xv.y, acc[1]);
                acc[2] = fmaf(w, xv.z, acc[2]); acc[3] = fmaf(w, xv.w, acc[3]);
            }
            #pragma unroll
            for (int p = 0; p < 4; p++)
                s_gx[(b*Nq + n0 + wrp*4 + p)*CIq + i] = acc[p];

            if (t < 64) {
                float aa = cst[0];
                #pragma unroll
                for (int c = 0; c < Cq; c++)
                    aa = fmaf(was[c], xs[c*68 + t], aa);
                s_a[b*Nq + n0 + t] = aa;
            }
            __syncthreads();
        }
    }
    gsync();

    // ========== P3: chunk totals (576 warps) + k* searches (576 warps) ==========
    {
        int w = t >> 5, lane = t & 31;
        int gwid = blockIdx.x * 16 + w;
        if (gwid < Bq*NCH) {
            int b = gwid / NCH, ch = gwid % NCH;
            int k0 = ch * CHSZ;
            int   mlane = s_perm[b*Nq + k0 + lane];
            float klane = s_keys[b*Nq + k0 + lane];
            const float* gxb = s_gx + b*Nq*CIq;
            float ag = 0.f, abg = 0.f;
            #pragma unroll
            for (int j = 0; j < 32; j++) {
                int   mm = __shfl_sync(0xffffffffu, mlane, j);
                float kk = __shfl_sync(0xffffffffu, klane, j);
                float gg = gxb[mm*CIq + lane];
                ag += gg;
                abg = fmaf(kk, gg, abg);
            }
            s_ctg [(b*NCH + ch)*CIq + lane] = ag;
            s_ctbg[(b*NCH + ch)*CIq + lane] = abg;
            if (blockIdx.x == 0 && w < Bq) {       // empty-suffix rows
                s_Sg [(w*NP1 + Nq)*CIq + lane] = 0.f;
                s_Sbg[(w*NP1 + Nq)*CIq + lane] = 0.f;
            }
        } else if (gwid < 2*Bq*NCH) {
            int idx = gwid - Bq*NCH;
            int b = idx / NCH;
            int p = (idx % NCH)*32 + lane;
            float thr = -s_a[b*Nq + p];
            const float* keys = s_keys + b*Nq;
            int lo = 0, hi = Nq;
            while (lo < hi) {
                int mid = (lo + hi) >> 1;
                if (keys[mid] <= thr) lo = mid + 1; else hi = mid;
            }
            s_kstar[b*Nq + p] = lo;
        }
    }
    gsync();

    // ========== P4: suffix-sum writes (4 warps per chunk = 2304 warps) ==========
    {
        int w = t >> 5, lane = t & 31;
        int gwid = blockIdx.x * 16 + w;
        if (gwid < Bq*NCH*4) {
            int cg = gwid >> 2, hc = gwid & 3;
            int b = cg / NCH, ch = cg % NCH;
            float rg = 0.f, rbg = 0.f;
            const float* ctg  = s_ctg  + b*NCH*CIq;
            const float* ctbg = s_ctbg + b*NCH*CIq;
            #pragma unroll 4
            for (int c2 = ch + 1; c2 < NCH; c2++) {
                rg  += ctg [c2*CIq + lane];
                rbg += ctbg[c2*CIq + lane];
            }
            int k0 = ch * CHSZ;
            int   mlane = s_perm[b*Nq + k0 + lane];
            float klane = s_keys[b*Nq + k0 + lane];
            const float* gxb = s_gx + b*Nq*CIq;
            int jstart = hc * 8;
            for (int j = 31; j >= jstart; j--) {
                int   mm = __shfl_sync(0xffffffffu, mlane, j);
                float kk = __shfl_sync(0xffffffffu, klane, j);
                float gg = gxb[mm*CIq + lane];
                rg += gg;
                rbg = fmaf(kk, gg, rbg);
                if (j < jstart + 8) {
                    s_Sg [(b*NP1 + k0 + j)*CIq + lane] = rg;
                    s_Sbg[(b*NP1 + k0 + j)*CIq + lane] = rbg;
                }
            }
        }
    }
    gsync();

    // ========== P5: y lookup + W projection + BN partials (1 tile/block) ========
    {
        float* ws   = (float*)SM;                   // 64*33 = 8448B
        float* ys   = (float*)(SM + 8448);          // 64*36 = 9216B
        float* a_sm = (float*)(SM + 17664);         // 64
        int*   k_sm = (int*)(SM + 17920);           // 64
        float* psum = (float*)(SM + 18176);         // 8*64
        float* psq  = (float*)(SM + 20224);         // 8*64

        for (int idx = t; idx < Cq*CIq; idx += NTHR)
            ws[(idx >> 5)*33 + (idx & 31)] = W_w[idx];
        __syncthreads();

        int c = t & 63, sub = t >> 6;               // sub: 0..7
        float wreg[CIq];
        #pragma unroll
        for (int i = 0; i < CIq; i++) wreg[i] = ws[c*33 + i];
        float wbc = W_b[c];

        for (int tile = blockIdx.x; tile < NTILE; tile += GRID) {
            int b = tile / TILES, n0 = (tile % TILES)*64;
            if (t < 64) {
                a_sm[t] = s_a[b*Nq + n0 + t];
                k_sm[t] = s_kstar[b*Nq + n0 + t];
            }
            __syncthreads();

            {
                int i = t & 31, wrp = t >> 5;
                #pragma unroll
                for (int p = 0; p < 4; p++) {
                    int pos = wrp*4 + p;
                    int k = k_sm[pos];
                    float sg  = s_Sg [(b*NP1 + k)*CIq + i];
                    float sbg = s_Sbg[(b*NP1 + k)*CIq + i];
                    ys[pos*36 + i] = fmaf(a_sm[pos], sg, sbg) * (1.0f / (float)Nq);
                }
            }
            __syncthreads();

            {
                float ls = 0.f, ls2 = 0.f;
                float* wyrow = s_wy + (b*Cq + c)*Nq + n0 + sub*8;
                #pragma unroll
                for (int q4 = 0; q4 < 2; q4++) {
                    float av[4];
                    #pragma unroll
                    for (int u = 0; u < 4; u++) {
                        int pos = sub*8 + q4*4 + u;
                        const float4* yv = (const float4*)&ys[pos*36];
                        float acc = 0.f;
                        #pragma unroll
                        for (int i4 = 0; i4 < CIq/4; i4++) {
                            float4 v = yv[i4];
                            acc = fmaf(wreg[i4*4+0], v.x, acc);
                            acc = fmaf(wreg[i4*4+1], v.y, acc);
                            acc = fmaf(wreg[i4*4+2], v.z, acc);
                            acc = fmaf(wreg[i4*4+3], v.w, acc);
                        }
                        av[u] = acc;
                        ls += acc; ls2 = fmaf(acc, acc, ls2);
                    }
                    float4 o;
                    o.x = av[0] + wbc; o.y = av[1] + wbc;
                    o.z = av[2] + wbc; o.w = av[3] + wbc;
                    *(float4*)(wyrow + q4*4) = o;
                }
                psum[sub*64 + c] = ls;
                psq [sub*64 + c] = ls2;
            }
            __syncthreads();

            if (t < 64) {
                float s = 0.f, s2 = 0.f;
                #pragma unroll
                for (int ss = 0; ss < 8; ss++) {
                    s  += psum[ss*64 + t];
                    s2 += psq [ss*64 + t];
                }
                s_part[(tile*Cq + t)*2 + 0] = s;
                s_part[(tile*Cq + t)*2 + 1] = s2;
            }
        }
    }
    gsync();

    // ========== P6: BN stats (redundant per block) + final ==========
    {
        float* red   = (float*)SM;            // [8][64]*2
        float* scale = (float*)(SM + 4096);   // 64
        float* shift = (float*)(SM + 4352);   // 64

        int c = t & 63, r = t >> 6;           // r: 0..7
        float s = 0.f, s2 = 0.f;
        const float2* pp = (const float2*)s_part;
        for (int blk = r; blk < NTILE; blk += 8) {
            float2 v = pp[blk*Cq + c];
            s += v.x; s2 += v.y;
        }
        red[r*64 + c] = s;
        red[512 + r*64 + c] = s2;
        __syncthreads();
        if (t < 64) {
            float ss = 0.f, qq = 0.f;
            #pragma unroll
            for (int rr = 0; rr < 8; rr++) {
                ss += red[rr*64 + t];
                qq += red[512 + rr*64 + t];
            }
            const float M = (float)(Bq * Nq);
            float mv = ss / M;
            float var = qq / M - mv*mv;
            float mean = W_b[t] + mv;
            float sc = bn_g[t] * rsqrtf(var + 1e-5f);
            scale[t] = sc;
            shift[t] = bn_b[t] - mean*sc;
        }
        __syncthreads();

        const int TOT4 = Bq*Cq*Nq/4;
        const float4* wy4 = (const float4*)s_wy;
        const float4* x4  = (const float4*)x;
        float4* o4 = (float4*)out;
        for (int i4 = blockIdx.x*NTHR + t; i4 < TOT4; i4 += GRID*NTHR) {
            int c2 = (i4 / (Nq/4)) & 63;
            float sc = scale[c2], sh = shift[c2];
            float4 w = wy4[i4];
            float4 xv = x4[i4];
            float4 o;
            o.x = fmaf(w.x, sc, sh) + xv.x;
            o.y = fmaf(w.y, sc, sh) + xv.y;
            o.z = fmaf(w.z, sc, sh) + xv.z;
            o.w = fmaf(w.w, sc, sh) + xv.w;
            o4[i4] = o;
        }
    }
}

// ---------------- launch ----------------
extern "C" void kernel_launch(void* const* d_in, const int* in_sizes, int n_in,
                              void* d_out, int out_size) {
    const float* x     = (const float*)d_in[0];
    const float* g_w   = (const float*)d_in[1];
    const float* g_b   = (const float*)d_in[2];
    const float* th_w  = (const float*)d_in[3];
    const float* th_b  = (const float*)d_in[4];
    const float* ph_w  = (const float*)d_in[5];
    const float* ph_b  = (const float*)d_in[6];
    const float* cp_wt = (const float*)d_in[7];
    const float* cp_wp = (const float*)d_in[8];
    const float* W_w   = (const float*)d_in[9];
    const float* W_b   = (const float*)d_in[10];
    const float* bn_g  = (const float*)d_in[11];
    const float* bn_b  = (const float*)d_in[12];
    float* out = (float*)d_out;

    fused_nonlocal<<<GRID, NTHR>>>(x, g_w, g_b, th_w, th_b, ph_w, ph_b,
                                   cp_wt, cp_wp, W_w, W_b, bn_g, bn_b, out);
}